// round 1
// baseline (speedup 1.0000x reference)
#include <cuda_runtime.h>
#include <math.h>

// ---------------- problem constants ----------------
#define CU   256                 // units
#define CL   128                 // seq len
#define CB   512                 // batch
#define CNR  65024               // CB*(CL-1) rows
#define CH   1024                // 4*U hidden
static __device__ __constant__ const float kNothing = 0.f; // (unused)

static constexpr float LR = 0.01f;
static constexpr float DREC_SCALE = 2.0f / (65024.0f * 256.0f); // 2/(N*U)

// ---------------- scratch layout (one __device__ array, no allocs) ----------------
static constexpr size_t SZ_NU = (size_t)CNR * CU;   // 16,646,144
static constexpr size_t SZ_NH = (size_t)CNR * CH;   // 66,584,576

static constexpr size_t O_X       = 0;
static constexpr size_t O_Y       = O_X   + SZ_NU;
static constexpr size_t O_PHI     = O_Y   + SZ_NU;
static constexpr size_t O_E       = O_PHI + SZ_NU;
static constexpr size_t O_Z       = O_E   + SZ_NU;
static constexpr size_t O_REC     = O_Z   + SZ_NU;
static constexpr size_t O_DZ      = O_REC + SZ_NU;
static constexpr size_t O_DE      = O_DZ  + SZ_NU;
static constexpr size_t O_PRE     = O_DE  + SZ_NU;   // also reused as dpre (in-place)
static constexpr size_t O_H       = O_PRE + SZ_NH;
static constexpr size_t O_MEAN    = O_H   + SZ_NH;
static constexpr size_t O_RSTD    = O_MEAN + CNR;
static constexpr size_t O_DW1     = O_RSTD + CNR;                   // 256*1024
static constexpr size_t O_DW2     = O_DW1 + (size_t)CU*CH;          // 1024*256
static constexpr size_t O_DB1     = O_DW2 + (size_t)CH*CU;          // 1024
static constexpr size_t O_DB2     = O_DB1 + CH;                     // 256
static constexpr size_t O_WGT     = O_DB2 + CU;                     // 256*256
static constexpr size_t O_W2T     = O_WGT + (size_t)CU*CU;          // 256*1024
static constexpr size_t O_PROJ    = O_W2T + (size_t)CU*CH;          // 512*256
static constexpr size_t O_PSI     = O_PROJ + (size_t)CB*CU;
static constexpr size_t O_PREPSI  = O_PSI  + (size_t)CB*CU;         // 512*1024
static constexpr size_t O_HPSI    = O_PREPSI + (size_t)CB*CH;
static constexpr size_t O_EPSI    = O_HPSI + (size_t)CB*CH;
static constexpr size_t O_CONTRIB = O_EPSI + (size_t)CB*CU;
static constexpr size_t O_END     = O_CONTRIB + (size_t)CB*CU;

__device__ float g_scratch[O_END];

// ---------------- math helpers ----------------
__device__ __forceinline__ float gelu_f(float x) {
    return 0.5f * x * (1.0f + erff(x * 0.7071067811865476f));
}
__device__ __forceinline__ float dgelu_f(float x) {
    float cdf = 0.5f * (1.0f + erff(x * 0.7071067811865476f));
    return cdf + x * 0.3989422804014327f * expf(-0.5f * x * x);
}

__device__ __forceinline__ float block_reduce_256(float v, float* sh) {
    int tid = threadIdx.x;
    #pragma unroll
    for (int o = 16; o; o >>= 1) v += __shfl_down_sync(0xffffffffu, v, o);
    if ((tid & 31) == 0) sh[tid >> 5] = v;
    __syncthreads();
    float r = sh[0] + sh[1] + sh[2] + sh[3] + sh[4] + sh[5] + sh[6] + sh[7];
    __syncthreads();
    return r;
}

// ---------------- generic NN GEMM: C = Aeff @ Beff (+bias) (+activation) ----------------
// Aeff = A (+A2), Beff = B (+b2s*B2), biaseff = bias (+bias2s*bias2)
// mode 0: none; mode 1: Caux=pre, C=gelu(pre); mode 2: C *= dgelu(aux) (aux may alias C)
// Requires: M%128==0 (grid.y), N%128==0 (grid.x), K%8==0, lda/ldb multiples of 4.
__global__ void __launch_bounds__(256) gemm_nn(
    const float* __restrict__ A, const float* __restrict__ A2,
    const float* __restrict__ B, const float* __restrict__ B2, float b2s,
    const float* __restrict__ bias, const float* __restrict__ bias2, float bias2s,
    float* __restrict__ C, float* __restrict__ Caux, const float* __restrict__ aux,
    int K, int lda, int ldb, int ldc, int mode)
{
    __shared__ float As[8][128];
    __shared__ float Bs[8][132];
    const int bm = blockIdx.y * 128, bn = blockIdx.x * 128;
    const int tid = threadIdx.x;
    const int a_m = tid >> 1, a_k4 = (tid & 1) * 4;
    const int b_k = tid >> 5, b_n4 = (tid & 31) * 4;
    const int tx = tid & 15, ty = tid >> 4;

    float acc[8][8];
    #pragma unroll
    for (int i = 0; i < 8; i++)
        #pragma unroll
        for (int j = 0; j < 8; j++) acc[i][j] = 0.f;

    const float* Aptr  = A + (size_t)(bm + a_m) * lda + a_k4;
    const float* A2ptr = A2 ? (A2 + (size_t)(bm + a_m) * lda + a_k4) : nullptr;

    for (int k0 = 0; k0 < K; k0 += 8) {
        float4 av = *(const float4*)(Aptr + k0);
        if (A2ptr) {
            float4 w = *(const float4*)(A2ptr + k0);
            av.x += w.x; av.y += w.y; av.z += w.z; av.w += w.w;
        }
        As[a_k4 + 0][a_m] = av.x; As[a_k4 + 1][a_m] = av.y;
        As[a_k4 + 2][a_m] = av.z; As[a_k4 + 3][a_m] = av.w;

        float4 bv = *(const float4*)(B + (size_t)(k0 + b_k) * ldb + bn + b_n4);
        if (B2) {
            float4 w = *(const float4*)(B2 + (size_t)(k0 + b_k) * ldb + bn + b_n4);
            bv.x += b2s * w.x; bv.y += b2s * w.y; bv.z += b2s * w.z; bv.w += b2s * w.w;
        }
        *(float4*)&Bs[b_k][b_n4] = bv;
        __syncthreads();

        #pragma unroll
        for (int kk = 0; kk < 8; kk++) {
            float a[8], b[8];
            #pragma unroll
            for (int i = 0; i < 8; i++) a[i] = As[kk][ty * 8 + i];
            #pragma unroll
            for (int j = 0; j < 8; j++) b[j] = Bs[kk][tx * 8 + j];
            #pragma unroll
            for (int i = 0; i < 8; i++)
                #pragma unroll
                for (int j = 0; j < 8; j++) acc[i][j] += a[i] * b[j];
        }
        __syncthreads();
    }

    #pragma unroll
    for (int i = 0; i < 8; i++) {
        const int m = bm + ty * 8 + i;
        const size_t rowc = (size_t)m * ldc;
        #pragma unroll
        for (int j = 0; j < 8; j++) {
            const int n = bn + tx * 8 + j;
            float c = acc[i][j];
            if (bias)  c += bias[n];
            if (bias2) c += bias2s * bias2[n];
            if (mode == 1) { Caux[rowc + n] = c; c = gelu_f(c); }
            else if (mode == 2) { c *= dgelu_f(aux[rowc + n]); }
            C[rowc + n] = c;
        }
    }
}

// ---------------- TN split-K GEMM with atomic accumulation: C += A^T @ B ----------------
// A is [K, M] row-major (lda), B is [K, N] row-major (ldb). Grid: (N/128, M/128, splits).
__global__ void __launch_bounds__(256) gemm_tn_splitk(
    const float* __restrict__ A, const float* __restrict__ B, float* __restrict__ C,
    int K, int lda, int ldb, int ldc, int kChunk)
{
    __shared__ float As[8][132];
    __shared__ float Bs[8][132];
    const int bm = blockIdx.y * 128, bn = blockIdx.x * 128;
    const int tid = threadIdx.x;
    const int l_k = tid >> 5, l_x4 = (tid & 31) * 4;
    const int tx = tid & 15, ty = tid >> 4;

    const int kb = blockIdx.z * kChunk;
    const int ke = min(K, kb + kChunk);

    float acc[8][8];
    #pragma unroll
    for (int i = 0; i < 8; i++)
        #pragma unroll
        for (int j = 0; j < 8; j++) acc[i][j] = 0.f;

    for (int k0 = kb; k0 < ke; k0 += 8) {
        *(float4*)&As[l_k][l_x4] = *(const float4*)(A + (size_t)(k0 + l_k) * lda + bm + l_x4);
        *(float4*)&Bs[l_k][l_x4] = *(const float4*)(B + (size_t)(k0 + l_k) * ldb + bn + l_x4);
        __syncthreads();
        #pragma unroll
        for (int kk = 0; kk < 8; kk++) {
            float a[8], b[8];
            #pragma unroll
            for (int i = 0; i < 8; i++) a[i] = As[kk][ty * 8 + i];
            #pragma unroll
            for (int j = 0; j < 8; j++) b[j] = Bs[kk][tx * 8 + j];
            #pragma unroll
            for (int i = 0; i < 8; i++)
                #pragma unroll
                for (int j = 0; j < 8; j++) acc[i][j] += a[i] * b[j];
        }
        __syncthreads();
    }

    #pragma unroll
    for (int i = 0; i < 8; i++) {
        const int m = bm + ty * 8 + i;
        #pragma unroll
        for (int j = 0; j < 8; j++) {
            atomicAdd(&C[(size_t)m * ldc + (bn + tx * 8 + j)], acc[i][j]);
        }
    }
}

// ---------------- small utility kernels ----------------
__global__ void zero_k(float* p, size_t n) {
    size_t i = (size_t)blockIdx.x * 256 + threadIdx.x;
    if (i < n) p[i] = 0.f;
}

// out[c*R + r] = in[r*C + c]  (R, C multiples of 32)
__global__ void transpose_k(const float* __restrict__ in, float* __restrict__ out, int R, int C) {
    __shared__ float t[32][33];
    int c0 = blockIdx.x * 32, r0 = blockIdx.y * 32;
    int x = threadIdx.x, y = threadIdx.y;
    #pragma unroll
    for (int dy = 0; dy < 32; dy += 8)
        t[y + dy][x] = in[(size_t)(r0 + y + dy) * C + c0 + x];
    __syncthreads();
    #pragma unroll
    for (int dy = 0; dy < 32; dy += 8)
        out[(size_t)(c0 + y + dy) * R + r0 + x] = t[x][y + dy];
}

// buf = [seq[:,1:,:], proj]; X = buf[:, :-1]; Y = buf[:, 1:]
__global__ void shift_k(const float* __restrict__ seq, const float* __restrict__ proj,
                        float* __restrict__ buf_out, float* __restrict__ X, float* __restrict__ Y) {
    size_t idx = (size_t)blockIdx.x * 256 + threadIdx.x;   // over CB*CL*CU
    int u = (int)(idx & (CU - 1));
    int t = (int)((idx >> 8) & (CL - 1));
    int b = (int)(idx >> 15);
    float val = (t < CL - 1) ? seq[(size_t)b * CL * CU + (size_t)(t + 1) * CU + u]
                             : proj[(size_t)b * CU + u];
    buf_out[idx] = val;
    if (t < CL - 1) X[((size_t)b * (CL - 1) + t) * CU + u] = val;
    if (t >= 1)     Y[((size_t)b * (CL - 1) + (t - 1)) * CU + u] = val;
}

__global__ void ln_fwd_k(const float* __restrict__ z, const float* __restrict__ g,
                         const float* __restrict__ bb, float* __restrict__ rec,
                         float* __restrict__ mean, float* __restrict__ rstd) {
    __shared__ float sh[8];
    const int row = blockIdx.x, tid = threadIdx.x;
    const size_t base = (size_t)row * CU;
    float v = z[base + tid];
    float m = block_reduce_256(v, sh) * (1.0f / CU);
    float d = v - m;
    float var = block_reduce_256(d * d, sh) * (1.0f / CU);
    float r = rsqrtf(var + 1e-3f);
    rec[base + tid] = g[tid] * d * r + bb[tid];
    if (tid == 0) { mean[row] = m; rstd[row] = r; }
}

__global__ void ln_bwd_k(const float* __restrict__ z, const float* __restrict__ rec,
                         const float* __restrict__ y, const float* __restrict__ g,
                         const float* __restrict__ mean, const float* __restrict__ rstd,
                         float* __restrict__ dz) {
    __shared__ float sh[8];
    const int row = blockIdx.x, tid = threadIdx.x;
    const size_t base = (size_t)row * CU;
    const float m = mean[row], r = rstd[row];
    float xhat = (z[base + tid] - m) * r;
    float drec = (rec[base + tid] - y[base + tid]) * DREC_SCALE;
    float dxh = drec * g[tid];
    float s1 = block_reduce_256(dxh, sh) * (1.0f / CU);
    float s2 = block_reduce_256(dxh * xhat, sh) * (1.0f / CU);
    dz[base + tid] = r * (dxh - s1 - xhat * s2);
}

// column sums: out[n] += sum_k A[k*N + n]   grid: (N/32, splits), block 256
__global__ void colsum_k(const float* __restrict__ A, float* __restrict__ out,
                         int K, int N, int kChunk) {
    __shared__ float sh[8][33];
    const int n = blockIdx.x * 32 + (threadIdx.x & 31);
    const int kl = threadIdx.x >> 5;
    const int kb = blockIdx.y * kChunk;
    const int ke = min(K, kb + kChunk);
    float s = 0.f;
    for (int k = kb + kl; k < ke; k += 8) s += A[(size_t)k * N + n];
    sh[kl][threadIdx.x & 31] = s;
    __syncthreads();
    if (kl == 0) {
        float t = 0.f;
        #pragma unroll
        for (int i = 0; i < 8; i++) t += sh[i][threadIdx.x & 31];
        atomicAdd(&out[n], t);
    }
}

__global__ void contrib_k(const float* __restrict__ rec, float* __restrict__ out) {
    const int b = blockIdx.x, u = threadIdx.x;
    const float* p = rec + (size_t)b * (CL - 1) * CU + u;
    float s = 0.f;
    for (int t = 0; t < CL - 1; t++) s += p[(size_t)t * CU];
    out[(size_t)b * CU + u] = s * (1.0f / (CL - 1));
}

// ---------------- launch ----------------
extern "C" void kernel_launch(void* const* d_in, const int* in_sizes, int n_in,
                              void* d_out, int out_size) {
    const float* inputs = (const float*)d_in[0];
    // d_in[1] = prev_hidden (unused by reference)
    const float* seq  = (const float*)d_in[2];
    const float* Wp   = (const float*)d_in[3];
    const float* bp   = (const float*)d_in[4];
    const float* Wphi = (const float*)d_in[5];
    const float* bphi = (const float*)d_in[6];
    const float* Wpsi = (const float*)d_in[7];
    const float* bpsi = (const float*)d_in[8];
    const float* W1   = (const float*)d_in[9];
    const float* b1   = (const float*)d_in[10];
    const float* W2   = (const float*)d_in[11];
    const float* b2   = (const float*)d_in[12];
    const float* Wg   = (const float*)d_in[13];
    const float* gb   = (const float*)d_in[14];
    const float* lng  = (const float*)d_in[15];
    const float* lnb  = (const float*)d_in[16];
    const float* Wh   = (const float*)d_in[17];
    const float* hb   = (const float*)d_in[18];

    float* out = (float*)d_out;                       // [512,256]
    float* buf_out = out + (size_t)CB * CU;           // [512,128,256]

    float* S = nullptr;
    cudaGetSymbolAddress((void**)&S, g_scratch);
    float *X = S + O_X, *Y = S + O_Y, *PHI = S + O_PHI, *E = S + O_E, *Z = S + O_Z;
    float *REC = S + O_REC, *DZ = S + O_DZ, *DE = S + O_DE, *PRE = S + O_PRE, *H = S + O_H;
    float *MEAN = S + O_MEAN, *RSTD = S + O_RSTD;
    float *DW1 = S + O_DW1, *DW2 = S + O_DW2, *DB1 = S + O_DB1, *DB2 = S + O_DB2;
    float *WGT = S + O_WGT, *W2T = S + O_W2T;
    float *PROJ = S + O_PROJ, *PSI = S + O_PSI, *PREPSI = S + O_PREPSI;
    float *HPSI = S + O_HPSI, *EPSI = S + O_EPSI, *CONTRIB = S + O_CONTRIB;

    // zero grad accumulators (dW1,dW2,db1,db2 are contiguous)
    {
        size_t nz = (size_t)CU * CH + (size_t)CH * CU + CH + CU;
        zero_k<<<(unsigned)((nz + 255) / 256), 256>>>(DW1, nz);
    }
    // weight transposes for backward NN GEMMs
    transpose_k<<<dim3(CU / 32, CU / 32), dim3(32, 8)>>>(Wg, WGT, CU, CU);
    transpose_k<<<dim3(CU / 32, CH / 32), dim3(32, 8)>>>(W2, W2T, CH, CU);

    // proj = inputs @ Wp + bp   [512,256]
    gemm_nn<<<dim3(CU / 128, CB / 128), 256>>>(inputs, nullptr, Wp, nullptr, 0.f,
        bp, nullptr, 0.f, PROJ, nullptr, nullptr, 128, 128, CU, CU, 0);

    // buf -> d_out, X, Y
    shift_k<<<(CB * CL * CU) / 256, 256>>>(seq, PROJ, buf_out, X, Y);

    // phi = X @ Wphi + bphi
    gemm_nn<<<dim3(CU / 128, CNR / 128), 256>>>(X, nullptr, Wphi, nullptr, 0.f,
        bphi, nullptr, 0.f, PHI, nullptr, nullptr, CU, CU, CU, CU, 0);

    // pre = phi @ W1 + b1 ; H = gelu(pre)
    gemm_nn<<<dim3(CH / 128, CNR / 128), 256>>>(PHI, nullptr, W1, nullptr, 0.f,
        b1, nullptr, 0.f, H, PRE, nullptr, CU, CU, CH, CH, 1);

    // e = H @ W2 + b2
    gemm_nn<<<dim3(CU / 128, CNR / 128), 256>>>(H, nullptr, W2, nullptr, 0.f,
        b2, nullptr, 0.f, E, nullptr, nullptr, CH, CH, CU, CU, 0);

    // z = e @ Wg + g_bias
    gemm_nn<<<dim3(CU / 128, CNR / 128), 256>>>(E, nullptr, Wg, nullptr, 0.f,
        gb, nullptr, 0.f, Z, nullptr, nullptr, CU, CU, CU, CU, 0);

    // rec = LN(z)
    ln_fwd_k<<<CNR, 256>>>(Z, lng, lnb, REC, MEAN, RSTD);

    // dz = LN_bwd(2*(rec-y)/(N*U))
    ln_bwd_k<<<CNR, 256>>>(Z, REC, Y, lng, MEAN, RSTD, DZ);

    // de = dz @ Wg^T
    gemm_nn<<<dim3(CU / 128, CNR / 128), 256>>>(DZ, nullptr, WGT, nullptr, 0.f,
        nullptr, nullptr, 0.f, DE, nullptr, nullptr, CU, CU, CU, CU, 0);

    // dW2 = H^T @ de  (split-K, atomic)
    gemm_tn_splitk<<<dim3(CU / 128, CH / 128, 32), 256>>>(H, DE, DW2, CNR, CH, CU, CU, 2032);
    // db2 = colsum(de)
    colsum_k<<<dim3(CU / 32, 32), 256>>>(DE, DB2, CNR, CU, 2032);

    // dpre = (de @ W2^T) * gelu'(pre)   (written in place over PRE)
    gemm_nn<<<dim3(CH / 128, CNR / 128), 256>>>(DE, nullptr, W2T, nullptr, 0.f,
        nullptr, nullptr, 0.f, PRE, nullptr, PRE, CU, CU, CH, CH, 2);

    // dW1 = phi^T @ dpre  (split-K, atomic)
    gemm_tn_splitk<<<dim3(CH / 128, CU / 128, 32), 256>>>(PHI, PRE, DW1, CNR, CU, CH, CH, 2032);
    // db1 = colsum(dpre)
    colsum_k<<<dim3(CH / 32, 32), 256>>>(PRE, DB1, CNR, CH, 2032);

    // contrib = mean_t rec
    contrib_k<<<CB, 256>>>(REC, CONTRIB);

    // psi = proj @ Wpsi + bpsi
    gemm_nn<<<dim3(CU / 128, CB / 128), 256>>>(PROJ, nullptr, Wpsi, nullptr, 0.f,
        bpsi, nullptr, 0.f, PSI, nullptr, nullptr, CU, CU, CU, CU, 0);

    // hpsi = gelu(psi @ (W1 - lr*dW1) + (b1 - lr*db1))
    gemm_nn<<<dim3(CH / 128, CB / 128), 256>>>(PSI, nullptr, W1, DW1, -LR,
        b1, DB1, -LR, HPSI, PREPSI, nullptr, CU, CU, CH, CH, 1);

    // epsi = hpsi @ (W2 - lr*dW2) + (b2 - lr*db2)
    gemm_nn<<<dim3(CU / 128, CB / 128), 256>>>(HPSI, nullptr, W2, DW2, -LR,
        b2, DB2, -LR, EPSI, nullptr, nullptr, CH, CH, CU, CU, 0);

    // out = (epsi + contrib) @ Wh + h_bias
    gemm_nn<<<dim3(CU / 128, CB / 128), 256>>>(EPSI, CONTRIB, Wh, nullptr, 0.f,
        hb, nullptr, 0.f, out, nullptr, nullptr, CU, CU, CU, CU, 0);

    (void)in_sizes; (void)n_in; (void)out_size;
}

// round 2
// speedup vs baseline: 2.0305x; 2.0305x over previous
#include <cuda_runtime.h>
#include <math.h>
#include <stdint.h>

// ---------------- problem constants ----------------
#define CU   256
#define CL   128
#define CB   512
#define CNR  65024               // CB*(CL-1)
#define CH   1024                // 4*U

static constexpr float LR = 0.01f;
static constexpr float DREC_SCALE = 2.0f / (65024.0f * 256.0f);

// ---------------- scratch ----------------
static constexpr size_t SZ_NU = (size_t)CNR * CU;
static constexpr size_t SZ_NH = (size_t)CNR * CH;

static constexpr size_t O_X      = 0;
static constexpr size_t O_Y      = O_X   + SZ_NU;
static constexpr size_t O_PHI    = O_Y   + SZ_NU;
static constexpr size_t O_E      = O_PHI + SZ_NU;
static constexpr size_t O_Z      = O_E   + SZ_NU;
static constexpr size_t O_REC    = O_Z   + SZ_NU;
static constexpr size_t O_DZ     = O_REC + SZ_NU;
static constexpr size_t O_DE     = O_DZ  + SZ_NU;
static constexpr size_t O_PRE    = O_DE  + SZ_NU;   // reused as dpre in-place
static constexpr size_t O_H      = O_PRE + SZ_NH;
static constexpr size_t O_DW1T   = O_H   + SZ_NH;                 // [1024,256]
static constexpr size_t O_DW2T   = O_DW1T + (size_t)CH*CU;        // [256,1024]
static constexpr size_t O_DB1    = O_DW2T + (size_t)CU*CH;
static constexpr size_t O_DB2    = O_DB1 + CH;
static constexpr size_t O_WPT    = O_DB2 + CU;                    // [256,128]
static constexpr size_t O_WPHIT  = O_WPT + (size_t)CU*128;
static constexpr size_t O_W1T    = O_WPHIT + (size_t)CU*CU;       // [1024,256]
static constexpr size_t O_W2T    = O_W1T + (size_t)CH*CU;         // [256,1024]
static constexpr size_t O_WGT    = O_W2T + (size_t)CU*CH;
static constexpr size_t O_WPSIT  = O_WGT + (size_t)CU*CU;
static constexpr size_t O_WHT    = O_WPSIT + (size_t)CU*CU;
static constexpr size_t O_PROJ   = O_WHT + (size_t)CU*CU;
static constexpr size_t O_PSI    = O_PROJ + (size_t)CB*CU;
static constexpr size_t O_PREPSI = O_PSI  + (size_t)CB*CU;
static constexpr size_t O_HPSI   = O_PREPSI + (size_t)CB*CH;
static constexpr size_t O_EPSI   = O_HPSI + (size_t)CB*CH;
static constexpr size_t O_CONTRIB= O_EPSI + (size_t)CB*CU;
static constexpr size_t O_END    = O_CONTRIB + (size_t)CB*CU;

__device__ float g_scratch[O_END];

// ---------------- helpers ----------------
__device__ __forceinline__ float gelu_f(float x) {
    return 0.5f * x * (1.0f + erff(x * 0.7071067811865476f));
}
__device__ __forceinline__ float dgelu_f(float x) {
    float cdf = 0.5f * (1.0f + erff(x * 0.7071067811865476f));
    return cdf + x * 0.3989422804014327f * expf(-0.5f * x * x);
}
__device__ __forceinline__ uint32_t f2tf(float x) {
    uint32_t r; asm("cvt.rna.tf32.f32 %0, %1;" : "=r"(r) : "f"(x)); return r;
}

#define LDSM4(r0,r1,r2,r3,addr) \
    asm volatile("ldmatrix.sync.aligned.m8n8.x4.shared.b16 {%0,%1,%2,%3}, [%4];" \
                 : "=r"(r0),"=r"(r1),"=r"(r2),"=r"(r3) : "r"(addr))

#define MMA_TF32(c,a0,a1,a2,a3,b0,b1) \
    asm volatile("mma.sync.aligned.m16n8k8.row.col.f32.tf32.tf32.f32 " \
                 "{%0,%1,%2,%3},{%4,%5,%6,%7},{%8,%9},{%0,%1,%2,%3};" \
                 : "+f"(c[0]),"+f"(c[1]),"+f"(c[2]),"+f"(c[3]) \
                 : "r"(a0),"r"(a1),"r"(a2),"r"(a3),"r"(b0),"r"(b1))

__device__ __forceinline__ float block_reduce_256(float v, float* sh) {
    int tid = threadIdx.x;
    #pragma unroll
    for (int o = 16; o; o >>= 1) v += __shfl_down_sync(0xffffffffu, v, o);
    if ((tid & 31) == 0) sh[tid >> 5] = v;
    __syncthreads();
    float r = sh[0] + sh[1] + sh[2] + sh[3] + sh[4] + sh[5] + sh[6] + sh[7];
    __syncthreads();
    return r;
}

// ---------------- tensor-core NN GEMM: C[M,N] = (A[M,K](+A2)) @ (BT[N,K](+b2s*B2T))^T ----------------
// block tile 128x256, BK=16, 8 warps (2x4) each 64x64.
// mode 0: bias only; 1: Caux=pre, C=gelu(pre); 2: C *= dgelu(aux)
__global__ void __launch_bounds__(256, 1) gemm_nn_tc(
    const float* __restrict__ A, const float* __restrict__ A2,
    const float* __restrict__ BT, const float* __restrict__ B2T, float b2s,
    const float* __restrict__ bias, const float* __restrict__ bias2, float bias2s,
    float* __restrict__ C, float* __restrict__ Caux, const float* __restrict__ aux,
    int K, int lda, int ldbt, int ldc, int mode)
{
    __shared__ uint32_t As[128 * 20];
    __shared__ uint32_t Bs[256 * 20];
    const int tid = threadIdx.x, lane = tid & 31, wid = tid >> 5;
    const int wm = wid & 1, wn = wid >> 1;
    const int g = lane >> 2, tig = lane & 3;
    const int bm = blockIdx.y * 128, bn = blockIdx.x * 256;

    float acc[4][8][4] = {};

    const uint32_t asBase = (uint32_t)__cvta_generic_to_shared(As);
    const uint32_t bsBase = (uint32_t)__cvta_generic_to_shared(Bs);
    // ldmatrix row addresses (byte offsets)
    const uint32_t aAddr0 = asBase + (((wm * 64 + (lane & 15)) * 20 + ((lane >> 4) << 2)) << 2);
    const uint32_t bAddr0 = bsBase + (((wn * 64 + (lane & 7) + ((lane & 16) ? 8 : 0)) * 20
                                      + ((lane & 8) ? 4 : 0)) << 2);

    for (int k0 = 0; k0 < K; k0 += 16) {
        #pragma unroll
        for (int r = 0; r < 2; r++) {
            int i = r * 256 + tid; int row = i >> 2; int kc = (i & 3) << 2;
            float4 v = *(const float4*)(A + (size_t)(bm + row) * lda + k0 + kc);
            if (A2) {
                float4 w = *(const float4*)(A2 + (size_t)(bm + row) * lda + k0 + kc);
                v.x += w.x; v.y += w.y; v.z += w.z; v.w += w.w;
            }
            uint32_t* d = &As[row * 20 + kc];
            d[0] = f2tf(v.x); d[1] = f2tf(v.y); d[2] = f2tf(v.z); d[3] = f2tf(v.w);
        }
        #pragma unroll
        for (int r = 0; r < 4; r++) {
            int i = r * 256 + tid; int row = i >> 2; int kc = (i & 3) << 2;
            float4 v = *(const float4*)(BT + (size_t)(bn + row) * ldbt + k0 + kc);
            if (B2T) {
                float4 w = *(const float4*)(B2T + (size_t)(bn + row) * ldbt + k0 + kc);
                v.x += b2s * w.x; v.y += b2s * w.y; v.z += b2s * w.z; v.w += b2s * w.w;
            }
            uint32_t* d = &Bs[row * 20 + kc];
            d[0] = f2tf(v.x); d[1] = f2tf(v.y); d[2] = f2tf(v.z); d[3] = f2tf(v.w);
        }
        __syncthreads();
        #pragma unroll
        for (int ks = 0; ks < 16; ks += 8) {
            uint32_t bq[16];
            #pragma unroll
            for (int nt2 = 0; nt2 < 4; nt2++) {
                uint32_t ad = bAddr0 + ((nt2 * 16 * 20 + ks) << 2);
                LDSM4(bq[nt2 * 4 + 0], bq[nt2 * 4 + 1], bq[nt2 * 4 + 2], bq[nt2 * 4 + 3], ad);
            }
            #pragma unroll
            for (int mt = 0; mt < 4; mt++) {
                uint32_t a0, a1, a2, a3;
                uint32_t ad = aAddr0 + ((mt * 16 * 20 + ks) << 2);
                LDSM4(a0, a1, a2, a3, ad);
                #pragma unroll
                for (int nt = 0; nt < 8; nt++) {
                    MMA_TF32(acc[mt][nt], a0, a1, a2, a3, bq[nt * 2], bq[nt * 2 + 1]);
                }
            }
        }
        __syncthreads();
    }

    #pragma unroll
    for (int mt = 0; mt < 4; mt++) {
        const int r0 = bm + wm * 64 + mt * 16 + g;
        #pragma unroll
        for (int nt = 0; nt < 8; nt++) {
            const int c = bn + wn * 64 + nt * 8 + tig * 2;
            float v0 = acc[mt][nt][0], v1 = acc[mt][nt][1];
            float v2 = acc[mt][nt][2], v3 = acc[mt][nt][3];
            if (bias) {
                float b0v = bias[c], b1v = bias[c + 1];
                if (bias2) { b0v += bias2s * bias2[c]; b1v += bias2s * bias2[c + 1]; }
                v0 += b0v; v1 += b1v; v2 += b0v; v3 += b1v;
            }
            const size_t i0 = (size_t)r0 * ldc + c;
            const size_t i1 = (size_t)(r0 + 8) * ldc + c;
            if (mode == 1) {
                *(float2*)&Caux[i0] = make_float2(v0, v1);
                *(float2*)&Caux[i1] = make_float2(v2, v3);
                v0 = gelu_f(v0); v1 = gelu_f(v1); v2 = gelu_f(v2); v3 = gelu_f(v3);
            } else if (mode == 2) {
                float2 x0 = *(const float2*)&aux[i0];
                float2 x1 = *(const float2*)&aux[i1];
                v0 *= dgelu_f(x0.x); v1 *= dgelu_f(x0.y);
                v2 *= dgelu_f(x1.x); v3 *= dgelu_f(x1.y);
            }
            *(float2*)&C[i0] = make_float2(v0, v1);
            *(float2*)&C[i1] = make_float2(v2, v3);
        }
    }
}

// ---------------- tensor-core TN split-K: C[M,N] += A[K,M]^T @ B[K,N] ----------------
// Fragments straight from global (coalesced 32B sectors, L1-shared across warps),
// register double-buffered. Grid (N/256, M/128, splits). 8 warps (2x4) x 64x64.
__global__ void __launch_bounds__(256, 1) gemm_tn_tc(
    const float* __restrict__ A, const float* __restrict__ B, float* __restrict__ C,
    int K, int lda, int ldb, int ldc, int kChunk)
{
    const int tid = threadIdx.x, lane = tid & 31, wid = tid >> 5;
    const int wm = wid & 1, wn = wid >> 1;
    const int g = lane >> 2, tig = lane & 3;
    const int bm = blockIdx.y * 128, bn = blockIdx.x * 256;
    const int kb = blockIdx.z * kChunk;
    const int ke = min(K, kb + kChunk);

    float acc[4][8][4] = {};

    const float* Abase = A + bm + wm * 64 + g;
    const float* Bbase = B + bn + wn * 64 + g;

    auto loadF = [&](uint32_t (&aF)[16], uint32_t (&bF)[16], int k) {
        const float* pa = Abase + (size_t)(k + tig) * lda;
        #pragma unroll
        for (int mt = 0; mt < 4; mt++) {
            const float* p = pa + mt * 16;
            aF[mt * 4 + 0] = __float_as_uint(p[0]);
            aF[mt * 4 + 1] = __float_as_uint(p[8]);
            aF[mt * 4 + 2] = __float_as_uint(p[(size_t)4 * lda]);
            aF[mt * 4 + 3] = __float_as_uint(p[(size_t)4 * lda + 8]);
        }
        const float* pb = Bbase + (size_t)(k + tig) * ldb;
        #pragma unroll
        for (int nt = 0; nt < 8; nt++) {
            bF[nt * 2 + 0] = __float_as_uint(pb[nt * 8]);
            bF[nt * 2 + 1] = __float_as_uint(pb[(size_t)4 * ldb + nt * 8]);
        }
    };
    auto mmaAll = [&](uint32_t (&aF)[16], uint32_t (&bF)[16]) {
        #pragma unroll
        for (int mt = 0; mt < 4; mt++)
            #pragma unroll
            for (int nt = 0; nt < 8; nt++)
                MMA_TF32(acc[mt][nt], aF[mt * 4], aF[mt * 4 + 1], aF[mt * 4 + 2], aF[mt * 4 + 3],
                         bF[nt * 2], bF[nt * 2 + 1]);
    };

    uint32_t aF0[16], bF0[16], aF1[16], bF1[16];
    loadF(aF0, bF0, kb);
    for (int k = kb; k < ke; k += 16) {
        if (k + 8 < ke) loadF(aF1, bF1, k + 8);
        mmaAll(aF0, bF0);
        if (k + 16 < ke) loadF(aF0, bF0, k + 16);
        if (k + 8 < ke) mmaAll(aF1, bF1);
    }

    #pragma unroll
    for (int mt = 0; mt < 4; mt++) {
        const int r0 = bm + wm * 64 + mt * 16 + g;
        #pragma unroll
        for (int nt = 0; nt < 8; nt++) {
            const int c = bn + wn * 64 + nt * 8 + tig * 2;
            atomicAdd(&C[(size_t)r0 * ldc + c],       acc[mt][nt][0]);
            atomicAdd(&C[(size_t)r0 * ldc + c + 1],   acc[mt][nt][1]);
            atomicAdd(&C[(size_t)(r0 + 8) * ldc + c],     acc[mt][nt][2]);
            atomicAdd(&C[(size_t)(r0 + 8) * ldc + c + 1], acc[mt][nt][3]);
        }
    }
}

// ---------------- small kernels ----------------
__global__ void zero_k(float* p, size_t n) {
    size_t i = (size_t)blockIdx.x * 256 + threadIdx.x;
    if (i < n) p[i] = 0.f;
}

__global__ void transpose_k(const float* __restrict__ in, float* __restrict__ out, int R, int C) {
    __shared__ float t[32][33];
    int c0 = blockIdx.x * 32, r0 = blockIdx.y * 32;
    int x = threadIdx.x, y = threadIdx.y;
    #pragma unroll
    for (int dy = 0; dy < 32; dy += 8)
        t[y + dy][x] = in[(size_t)(r0 + y + dy) * C + c0 + x];
    __syncthreads();
    #pragma unroll
    for (int dy = 0; dy < 32; dy += 8)
        out[(size_t)(c0 + y + dy) * R + r0 + x] = t[x][y + dy];
}

__global__ void shift_k(const float* __restrict__ seq, const float* __restrict__ proj,
                        float* __restrict__ buf_out, float* __restrict__ X, float* __restrict__ Y) {
    size_t idx = (size_t)blockIdx.x * 256 + threadIdx.x;
    int u = (int)(idx & (CU - 1));
    int t = (int)((idx >> 8) & (CL - 1));
    int b = (int)(idx >> 15);
    float val = (t < CL - 1) ? seq[(size_t)b * CL * CU + (size_t)(t + 1) * CU + u]
                             : proj[(size_t)b * CU + u];
    buf_out[idx] = val;
    if (t < CL - 1) X[((size_t)b * (CL - 1) + t) * CU + u] = val;
    if (t >= 1)     Y[((size_t)b * (CL - 1) + (t - 1)) * CU + u] = val;
}

__global__ void ln_fused_k(const float* __restrict__ z, const float* __restrict__ y,
                           const float* __restrict__ g, const float* __restrict__ bb,
                           float* __restrict__ rec, float* __restrict__ dz) {
    __shared__ float sh[8];
    const int row = blockIdx.x, tid = threadIdx.x;
    const size_t base = (size_t)row * CU;
    float v = z[base + tid];
    float m = block_reduce_256(v, sh) * (1.0f / CU);
    float d = v - m;
    float var = block_reduce_256(d * d, sh) * (1.0f / CU);
    float r = rsqrtf(var + 1e-3f);
    float xh = d * r;
    float gg = g[tid];
    float recv = gg * xh + bb[tid];
    rec[base + tid] = recv;
    float drec = (recv - y[base + tid]) * DREC_SCALE;
    float dxh = drec * gg;
    float s1 = block_reduce_256(dxh, sh) * (1.0f / CU);
    float s2 = block_reduce_256(dxh * xh, sh) * (1.0f / CU);
    dz[base + tid] = r * (dxh - s1 - xh * s2);
}

__global__ void colsum_k(const float* __restrict__ A, float* __restrict__ out,
                         int K, int N, int kChunk) {
    __shared__ float sh[8][33];
    const int n = blockIdx.x * 32 + (threadIdx.x & 31);
    const int kl = threadIdx.x >> 5;
    const int kb = blockIdx.y * kChunk;
    const int ke = min(K, kb + kChunk);
    float s = 0.f;
    for (int k = kb + kl; k < ke; k += 8) s += A[(size_t)k * N + n];
    sh[kl][threadIdx.x & 31] = s;
    __syncthreads();
    if (kl == 0) {
        float t = 0.f;
        #pragma unroll
        for (int i = 0; i < 8; i++) t += sh[i][threadIdx.x & 31];
        atomicAdd(&out[n], t);
    }
}

__global__ void contrib_k(const float* __restrict__ rec, float* __restrict__ out) {
    const int b = blockIdx.x, u = threadIdx.x;
    const float* p = rec + (size_t)b * (CL - 1) * CU + u;
    float s = 0.f;
    for (int t = 0; t < CL - 1; t++) s += p[(size_t)t * CU];
    out[(size_t)b * CU + u] = s * (1.0f / (CL - 1));
}

// ---------------- launch ----------------
extern "C" void kernel_launch(void* const* d_in, const int* in_sizes, int n_in,
                              void* d_out, int out_size) {
    const float* inputs = (const float*)d_in[0];
    const float* seq  = (const float*)d_in[2];
    const float* Wp   = (const float*)d_in[3];
    const float* bp   = (const float*)d_in[4];
    const float* Wphi = (const float*)d_in[5];
    const float* bphi = (const float*)d_in[6];
    const float* Wpsi = (const float*)d_in[7];
    const float* bpsi = (const float*)d_in[8];
    const float* W1   = (const float*)d_in[9];
    const float* b1   = (const float*)d_in[10];
    const float* W2   = (const float*)d_in[11];
    const float* b2   = (const float*)d_in[12];
    const float* Wg   = (const float*)d_in[13];
    const float* gb   = (const float*)d_in[14];
    const float* lng  = (const float*)d_in[15];
    const float* lnb  = (const float*)d_in[16];
    const float* Wh   = (const float*)d_in[17];
    const float* hb   = (const float*)d_in[18];

    float* out = (float*)d_out;
    float* buf_out = out + (size_t)CB * CU;

    float* S = nullptr;
    cudaGetSymbolAddress((void**)&S, g_scratch);
    float *X = S + O_X, *Y = S + O_Y, *PHI = S + O_PHI, *E = S + O_E, *Z = S + O_Z;
    float *REC = S + O_REC, *DZ = S + O_DZ, *DE = S + O_DE, *PRE = S + O_PRE, *H = S + O_H;
    float *DW1T = S + O_DW1T, *DW2T = S + O_DW2T, *DB1 = S + O_DB1, *DB2 = S + O_DB2;
    float *WpT = S + O_WPT, *WphiT = S + O_WPHIT, *W1T = S + O_W1T, *W2T = S + O_W2T;
    float *WgT = S + O_WGT, *WpsiT = S + O_WPSIT, *WhT = S + O_WHT;
    float *PROJ = S + O_PROJ, *PSI = S + O_PSI, *PREPSI = S + O_PREPSI;
    float *HPSI = S + O_HPSI, *EPSI = S + O_EPSI, *CONTRIB = S + O_CONTRIB;

    { // zero dW1T,dW2T,db1,db2 (contiguous)
        size_t nz = (size_t)CH * CU + (size_t)CU * CH + CH + CU;
        zero_k<<<(unsigned)((nz + 255) / 256), 256>>>(DW1T, nz);
    }
    // weight transposes (tiny)
    transpose_k<<<dim3(CU / 32, 128 / 32), dim3(32, 8)>>>(Wp,   WpT,   128, CU);
    transpose_k<<<dim3(CU / 32, CU / 32),  dim3(32, 8)>>>(Wphi, WphiT, CU, CU);
    transpose_k<<<dim3(CH / 32, CU / 32),  dim3(32, 8)>>>(W1,   W1T,   CU, CH);
    transpose_k<<<dim3(CU / 32, CH / 32),  dim3(32, 8)>>>(W2,   W2T,   CH, CU);
    transpose_k<<<dim3(CU / 32, CU / 32),  dim3(32, 8)>>>(Wg,   WgT,   CU, CU);
    transpose_k<<<dim3(CU / 32, CU / 32),  dim3(32, 8)>>>(Wpsi, WpsiT, CU, CU);
    transpose_k<<<dim3(CU / 32, CU / 32),  dim3(32, 8)>>>(Wh,   WhT,   CU, CU);

    // proj = inputs @ Wp + bp    [512,256]
    gemm_nn_tc<<<dim3(1, CB / 128), 256>>>(inputs, nullptr, WpT, nullptr, 0.f,
        bp, nullptr, 0.f, PROJ, nullptr, nullptr, 128, 128, 128, CU, 0);

    shift_k<<<(CB * CL * CU) / 256, 256>>>(seq, PROJ, buf_out, X, Y);

    // phi = X @ Wphi + bphi
    gemm_nn_tc<<<dim3(1, CNR / 128), 256>>>(X, nullptr, WphiT, nullptr, 0.f,
        bphi, nullptr, 0.f, PHI, nullptr, nullptr, CU, CU, CU, CU, 0);

    // pre = phi@W1+b1 ; H = gelu(pre)
    gemm_nn_tc<<<dim3(CH / 256, CNR / 128), 256>>>(PHI, nullptr, W1T, nullptr, 0.f,
        b1, nullptr, 0.f, H, PRE, nullptr, CU, CU, CU, CH, 1);

    // e = H @ W2 + b2
    gemm_nn_tc<<<dim3(1, CNR / 128), 256>>>(H, nullptr, W2T, nullptr, 0.f,
        b2, nullptr, 0.f, E, nullptr, nullptr, CH, CH, CH, CU, 0);

    // z = e @ Wg + g_bias
    gemm_nn_tc<<<dim3(1, CNR / 128), 256>>>(E, nullptr, WgT, nullptr, 0.f,
        gb, nullptr, 0.f, Z, nullptr, nullptr, CU, CU, CU, CU, 0);

    // rec = LN(z); dz = LN_bwd(2*(rec-y)/(N*U))
    ln_fused_k<<<CNR, 256>>>(Z, Y, lng, lnb, REC, DZ);

    // de = dz @ Wg^T   (B^T = Wg directly)
    gemm_nn_tc<<<dim3(1, CNR / 128), 256>>>(DZ, nullptr, Wg, nullptr, 0.f,
        nullptr, nullptr, 0.f, DE, nullptr, nullptr, CU, CU, CU, CU, 0);

    // dW2T = de^T @ H   [256,1024]
    gemm_tn_tc<<<dim3(CH / 256, CU / 128, 32), 256>>>(DE, H, DW2T, CNR, CU, CH, CH, 2032);
    colsum_k<<<dim3(CU / 32, 32), 256>>>(DE, DB2, CNR, CU, 2032);

    // dpre = (de @ W2^T) * gelu'(pre)   (B^T = W2 directly; in-place over PRE)
    gemm_nn_tc<<<dim3(CH / 256, CNR / 128), 256>>>(DE, nullptr, W2, nullptr, 0.f,
        nullptr, nullptr, 0.f, PRE, nullptr, PRE, CU, CU, CU, CH, 2);

    // dW1T = dpre^T @ phi   [1024,256]
    gemm_tn_tc<<<dim3(1, CH / 128, 32), 256>>>(PRE, PHI, DW1T, CNR, CH, CU, CU, 2032);
    colsum_k<<<dim3(CH / 32, 32), 256>>>(PRE, DB1, CNR, CH, 2032);

    contrib_k<<<CB, 256>>>(REC, CONTRIB);

    // psi = proj @ Wpsi + bpsi
    gemm_nn_tc<<<dim3(1, CB / 128), 256>>>(PROJ, nullptr, WpsiT, nullptr, 0.f,
        bpsi, nullptr, 0.f, PSI, nullptr, nullptr, CU, CU, CU, CU, 0);

    // hpsi = gelu(psi @ (W1 - lr dW1) + (b1 - lr db1))
    gemm_nn_tc<<<dim3(CH / 256, CB / 128), 256>>>(PSI, nullptr, W1T, DW1T, -LR,
        b1, DB1, -LR, HPSI, PREPSI, nullptr, CU, CU, CU, CH, 1);

    // epsi = hpsi @ (W2 - lr dW2) + (b2 - lr db2)
    gemm_nn_tc<<<dim3(1, CB / 128), 256>>>(HPSI, nullptr, W2T, DW2T, -LR,
        b2, DB2, -LR, EPSI, nullptr, nullptr, CH, CH, CH, CU, 0);

    // out = (epsi + contrib) @ Wh + h_bias
    gemm_nn_tc<<<dim3(1, CB / 128), 256>>>(EPSI, CONTRIB, WhT, nullptr, 0.f,
        hb, nullptr, 0.f, out, nullptr, nullptr, CU, CU, CU, CU, 0);

    (void)in_sizes; (void)n_in; (void)out_size;
}

// round 3
// speedup vs baseline: 2.5078x; 1.2350x over previous
#include <cuda_runtime.h>
#include <math.h>
#include <stdint.h>

// ---------------- problem constants ----------------
#define CU   256
#define CL   128
#define CB   512
#define CNR  65024               // CB*(CL-1)
#define CH   1024                // 4*U

static constexpr float LR = 0.01f;
static constexpr float DREC_SCALE = 2.0f / (65024.0f * 256.0f);

// ---------------- scratch ----------------
static constexpr size_t SZ_NU = (size_t)CNR * CU;
static constexpr size_t SZ_NH = (size_t)CNR * CH;

static constexpr size_t O_PHI    = 0;
static constexpr size_t O_Z      = O_PHI + SZ_NU;
static constexpr size_t O_REC    = O_Z   + SZ_NU;
static constexpr size_t O_DZ     = O_REC + SZ_NU;
static constexpr size_t O_DE     = O_DZ  + SZ_NU;
static constexpr size_t O_PRE    = O_DE  + SZ_NU;   // reused as dpre in-place
static constexpr size_t O_H      = O_PRE + SZ_NH;
static constexpr size_t O_DW1T   = O_H   + SZ_NH;                 // [1024,256]
static constexpr size_t O_DW2T   = O_DW1T + (size_t)CH*CU;        // [256,1024]
static constexpr size_t O_DB1    = O_DW2T + (size_t)CU*CH;
static constexpr size_t O_DB2    = O_DB1 + CH;
static constexpr size_t O_WPT    = O_DB2 + CU;                    // [256,128]
static constexpr size_t O_WPHIT  = O_WPT + (size_t)CU*128;
static constexpr size_t O_W1T    = O_WPHIT + (size_t)CU*CU;       // [1024,256]
static constexpr size_t O_W2T    = O_W1T + (size_t)CH*CU;         // [256,1024]
static constexpr size_t O_WGT    = O_W2T + (size_t)CU*CH;
static constexpr size_t O_WPSIT  = O_WGT + (size_t)CU*CU;
static constexpr size_t O_WHT    = O_WPSIT + (size_t)CU*CU;
static constexpr size_t O_COMBT  = O_WHT + (size_t)CU*CU;         // (W2@Wg)^T [256,1024]
static constexpr size_t O_ZB     = O_COMBT + (size_t)CU*CH;       // [256]
static constexpr size_t O_PROJ   = O_ZB + CU;
static constexpr size_t O_PSI    = O_PROJ + (size_t)CB*CU;
static constexpr size_t O_PREPSI = O_PSI  + (size_t)CB*CU;
static constexpr size_t O_HPSI   = O_PREPSI + (size_t)CB*CH;
static constexpr size_t O_EPSI   = O_HPSI + (size_t)CB*CH;
static constexpr size_t O_CONTRIB= O_EPSI + (size_t)CB*CU;
static constexpr size_t O_END    = O_CONTRIB + (size_t)CB*CU;

__device__ float g_scratch[O_END];

// ---------------- helpers ----------------
__device__ __forceinline__ float gelu_f(float x) {
    return 0.5f * x * (1.0f + erff(x * 0.7071067811865476f));
}
__device__ __forceinline__ float dgelu_f(float x) {
    float cdf = 0.5f * (1.0f + erff(x * 0.7071067811865476f));
    return cdf + x * 0.3989422804014327f * expf(-0.5f * x * x);
}
__device__ __forceinline__ uint32_t f2tf(float x) {
    uint32_t r; asm("cvt.rna.tf32.f32 %0, %1;" : "=r"(r) : "f"(x)); return r;
}

#define LDSM4(r0,r1,r2,r3,addr) \
    asm volatile("ldmatrix.sync.aligned.m8n8.x4.shared.b16 {%0,%1,%2,%3}, [%4];" \
                 : "=r"(r0),"=r"(r1),"=r"(r2),"=r"(r3) : "r"(addr))

#define MMA_TF32(c,a0,a1,a2,a3,b0,b1) \
    asm volatile("mma.sync.aligned.m16n8k8.row.col.f32.tf32.tf32.f32 " \
                 "{%0,%1,%2,%3},{%4,%5,%6,%7},{%8,%9},{%0,%1,%2,%3};" \
                 : "+f"(c[0]),"+f"(c[1]),"+f"(c[2]),"+f"(c[3]) \
                 : "r"(a0),"r"(a1),"r"(a2),"r"(a3),"r"(b0),"r"(b1))

__device__ __forceinline__ float block_reduce_256(float v, float* sh) {
    int tid = threadIdx.x;
    #pragma unroll
    for (int o = 16; o; o >>= 1) v += __shfl_down_sync(0xffffffffu, v, o);
    if ((tid & 31) == 0) sh[tid >> 5] = v;
    __syncthreads();
    float r = sh[0] + sh[1] + sh[2] + sh[3] + sh[4] + sh[5] + sh[6] + sh[7];
    __syncthreads();
    return r;
}

// ---------------- pipelined tensor-core NN GEMM ----------------
// C[M,N] = (A[M,K](+A2)) @ (BT[N,K](+b2s*B2T))^T, tile 128x256, BK=16, 8 warps.
// amap!=0: A row r is fetched from row (r + r/127) of A (shifted-buffer gather).
// mode 0: bias only; 1: Caux=pre, C=gelu(pre); 2: C *= dgelu(aux)
// colsum_out!=nullptr: atomically accumulates column sums of final C.
static constexpr int AS_STRIDE = 20;
static constexpr int A_BUFW = 128 * AS_STRIDE;   // words per A stage
static constexpr int B_BUFW = 256 * AS_STRIDE;   // words per B stage
static constexpr int GEMM_SMEM_BYTES = (2 * A_BUFW + 2 * B_BUFW) * 4;  // 61440

__global__ void __launch_bounds__(256, 1) gemm_nn_tc(
    const float* __restrict__ A, const float* __restrict__ A2,
    const float* __restrict__ BT, const float* __restrict__ B2T, float b2s,
    const float* __restrict__ bias, const float* __restrict__ bias2, float bias2s,
    float* __restrict__ C, float* __restrict__ Caux, const float* __restrict__ aux,
    float* __restrict__ colsum_out,
    int K, int lda, int ldbt, int ldc, int mode, int amap)
{
    extern __shared__ uint32_t sm[];
    // layout: A0 | A1 | B0 | B1
    uint32_t* AsBuf = sm;
    uint32_t* BsBuf = sm + 2 * A_BUFW;

    const int tid = threadIdx.x, lane = tid & 31, wid = tid >> 5;
    const int wm = wid & 1, wn = wid >> 1;
    const int g = lane >> 2, tig = lane & 3;
    const int bm = blockIdx.y * 128, bn = blockIdx.x * 256;

    float acc[4][8][4] = {};

    const uint32_t smBase = (uint32_t)__cvta_generic_to_shared(sm);
    const uint32_t aAddr0 = smBase + (((wm * 64 + (lane & 15)) * AS_STRIDE + ((lane >> 4) << 2)) << 2);
    const uint32_t bAddr0 = smBase + ((2 * A_BUFW
                          + (wn * 64 + (lane & 7) + ((lane & 16) ? 8 : 0)) * AS_STRIDE
                          + ((lane & 8) ? 4 : 0)) << 2);

    // per-thread ldg/sts coordinates
    const int a_row = tid >> 2, a_kc = (tid & 3) << 2;       // + r*256 rows pattern (2 reps)
    float4 ra[2], rb[4];

    auto ldgAll = [&](int k0) {
        #pragma unroll
        for (int r = 0; r < 2; r++) {
            int row = (r * 256 + tid) >> 2; int kc = ((r * 256 + tid) & 3) << 2;
            int grow = bm + row;
            if (amap) grow += (int)((unsigned)grow / 127u);
            float4 v = *(const float4*)(A + (size_t)grow * lda + k0 + kc);
            if (A2) {
                float4 w = *(const float4*)(A2 + (size_t)(bm + row) * lda + k0 + kc);
                v.x += w.x; v.y += w.y; v.z += w.z; v.w += w.w;
            }
            ra[r] = v;
        }
        #pragma unroll
        for (int r = 0; r < 4; r++) {
            int row = (r * 256 + tid) >> 2; int kc = ((r * 256 + tid) & 3) << 2;
            float4 v = *(const float4*)(BT + (size_t)(bn + row) * ldbt + k0 + kc);
            if (B2T) {
                float4 w = *(const float4*)(B2T + (size_t)(bn + row) * ldbt + k0 + kc);
                v.x += b2s * w.x; v.y += b2s * w.y; v.z += b2s * w.z; v.w += b2s * w.w;
            }
            rb[r] = v;
        }
    };
    auto stsAll = [&](int buf) {
        #pragma unroll
        for (int r = 0; r < 2; r++) {
            int row = (r * 256 + tid) >> 2; int kc = ((r * 256 + tid) & 3) << 2;
            uint32_t* d = &AsBuf[buf * A_BUFW + row * AS_STRIDE + kc];
            d[0] = f2tf(ra[r].x); d[1] = f2tf(ra[r].y); d[2] = f2tf(ra[r].z); d[3] = f2tf(ra[r].w);
        }
        #pragma unroll
        for (int r = 0; r < 4; r++) {
            int row = (r * 256 + tid) >> 2; int kc = ((r * 256 + tid) & 3) << 2;
            uint32_t* d = &BsBuf[buf * B_BUFW + row * AS_STRIDE + kc];
            d[0] = f2tf(rb[r].x); d[1] = f2tf(rb[r].y); d[2] = f2tf(rb[r].z); d[3] = f2tf(rb[r].w);
        }
    };

    // prologue
    ldgAll(0);
    stsAll(0);
    if (K > 16) ldgAll(16);
    __syncthreads();

    int cur = 0;
    for (int k0 = 0; k0 < K; k0 += 16) {
        const bool hasNext = (k0 + 16 < K);
        if (hasNext) stsAll(cur ^ 1);            // stage k0+16 into other buffer
        if (k0 + 32 < K) ldgAll(k0 + 32);        // start fetching k0+32

        const uint32_t aOff = (uint32_t)(cur * A_BUFW * 4);
        const uint32_t bOff = (uint32_t)(cur * B_BUFW * 4);
        #pragma unroll
        for (int ks = 0; ks < 16; ks += 8) {
            uint32_t bq[16];
            #pragma unroll
            for (int nt2 = 0; nt2 < 4; nt2++) {
                uint32_t ad = bAddr0 + bOff + ((nt2 * 16 * AS_STRIDE + ks) << 2);
                LDSM4(bq[nt2 * 4 + 0], bq[nt2 * 4 + 1], bq[nt2 * 4 + 2], bq[nt2 * 4 + 3], ad);
            }
            #pragma unroll
            for (int mt = 0; mt < 4; mt++) {
                uint32_t a0, a1, a2, a3;
                uint32_t ad = aAddr0 + aOff + ((mt * 16 * AS_STRIDE + ks) << 2);
                LDSM4(a0, a1, a2, a3, ad);
                #pragma unroll
                for (int nt = 0; nt < 8; nt++)
                    MMA_TF32(acc[mt][nt], a0, a1, a2, a3, bq[nt * 2], bq[nt * 2 + 1]);
            }
        }
        __syncthreads();
        cur ^= 1;
    }

    // ---------------- epilogue ----------------
    float csum[8][2];
    #pragma unroll
    for (int nt = 0; nt < 8; nt++) { csum[nt][0] = 0.f; csum[nt][1] = 0.f; }

    #pragma unroll
    for (int mt = 0; mt < 4; mt++) {
        const int r0 = bm + wm * 64 + mt * 16 + g;
        #pragma unroll
        for (int nt = 0; nt < 8; nt++) {
            const int c = bn + wn * 64 + nt * 8 + tig * 2;
            float v0 = acc[mt][nt][0], v1 = acc[mt][nt][1];
            float v2 = acc[mt][nt][2], v3 = acc[mt][nt][3];
            if (bias) {
                float b0v = bias[c], b1v = bias[c + 1];
                if (bias2) { b0v += bias2s * bias2[c]; b1v += bias2s * bias2[c + 1]; }
                v0 += b0v; v1 += b1v; v2 += b0v; v3 += b1v;
            }
            const size_t i0 = (size_t)r0 * ldc + c;
            const size_t i1 = (size_t)(r0 + 8) * ldc + c;
            if (mode == 1) {
                *(float2*)&Caux[i0] = make_float2(v0, v1);
                *(float2*)&Caux[i1] = make_float2(v2, v3);
                v0 = gelu_f(v0); v1 = gelu_f(v1); v2 = gelu_f(v2); v3 = gelu_f(v3);
            } else if (mode == 2) {
                float2 x0 = *(const float2*)&aux[i0];
                float2 x1 = *(const float2*)&aux[i1];
                v0 *= dgelu_f(x0.x); v1 *= dgelu_f(x0.y);
                v2 *= dgelu_f(x1.x); v3 *= dgelu_f(x1.y);
            }
            *(float2*)&C[i0] = make_float2(v0, v1);
            *(float2*)&C[i1] = make_float2(v2, v3);
            if (colsum_out) { csum[nt][0] += v0 + v2; csum[nt][1] += v1 + v3; }
        }
    }

    if (colsum_out) {
        __syncthreads();
        float* cs = (float*)sm;          // reuse smem
        if (tid < 256) cs[tid] = 0.f;
        __syncthreads();
        #pragma unroll
        for (int nt = 0; nt < 8; nt++) {
            #pragma unroll
            for (int j = 0; j < 2; j++) {
                float v = csum[nt][j];
                v += __shfl_xor_sync(0xffffffffu, v, 4);
                v += __shfl_xor_sync(0xffffffffu, v, 8);
                v += __shfl_xor_sync(0xffffffffu, v, 16);
                if (g == 0) atomicAdd(&cs[wn * 64 + nt * 8 + tig * 2 + j], v);
            }
        }
        __syncthreads();
        if (tid < 256) atomicAdd(&colsum_out[bn + tid], cs[tid]);
    }
}

// ---------------- tensor-core TN split-K: C[M,N] += A[K,M]^T @ B[K,N] ----------------
__global__ void __launch_bounds__(256, 1) gemm_tn_tc(
    const float* __restrict__ A, const float* __restrict__ B, float* __restrict__ C,
    int K, int lda, int ldb, int ldc, int kChunk)
{
    const int tid = threadIdx.x, lane = tid & 31, wid = tid >> 5;
    const int wm = wid & 1, wn = wid >> 1;
    const int g = lane >> 2, tig = lane & 3;
    const int bm = blockIdx.y * 128, bn = blockIdx.x * 256;
    const int kb = blockIdx.z * kChunk;
    const int ke = min(K, kb + kChunk);

    float acc[4][8][4] = {};

    const float* Abase = A + bm + wm * 64 + g;
    const float* Bbase = B + bn + wn * 64 + g;

    auto loadF = [&](uint32_t (&aF)[16], uint32_t (&bF)[16], int k) {
        const float* pa = Abase + (size_t)(k + tig) * lda;
        #pragma unroll
        for (int mt = 0; mt < 4; mt++) {
            const float* p = pa + mt * 16;
            aF[mt * 4 + 0] = __float_as_uint(p[0]);
            aF[mt * 4 + 1] = __float_as_uint(p[8]);
            aF[mt * 4 + 2] = __float_as_uint(p[(size_t)4 * lda]);
            aF[mt * 4 + 3] = __float_as_uint(p[(size_t)4 * lda + 8]);
        }
        const float* pb = Bbase + (size_t)(k + tig) * ldb;
        #pragma unroll
        for (int nt = 0; nt < 8; nt++) {
            bF[nt * 2 + 0] = __float_as_uint(pb[nt * 8]);
            bF[nt * 2 + 1] = __float_as_uint(pb[(size_t)4 * ldb + nt * 8]);
        }
    };
    auto mmaAll = [&](uint32_t (&aF)[16], uint32_t (&bF)[16]) {
        #pragma unroll
        for (int mt = 0; mt < 4; mt++)
            #pragma unroll
            for (int nt = 0; nt < 8; nt++)
                MMA_TF32(acc[mt][nt], aF[mt * 4], aF[mt * 4 + 1], aF[mt * 4 + 2], aF[mt * 4 + 3],
                         bF[nt * 2], bF[nt * 2 + 1]);
    };

    uint32_t aF0[16], bF0[16], aF1[16], bF1[16];
    loadF(aF0, bF0, kb);
    for (int k = kb; k < ke; k += 16) {
        if (k + 8 < ke) loadF(aF1, bF1, k + 8);
        mmaAll(aF0, bF0);
        if (k + 16 < ke) loadF(aF0, bF0, k + 16);
        if (k + 8 < ke) mmaAll(aF1, bF1);
    }

    #pragma unroll
    for (int mt = 0; mt < 4; mt++) {
        const int r0 = bm + wm * 64 + mt * 16 + g;
        #pragma unroll
        for (int nt = 0; nt < 8; nt++) {
            const int c = bn + wn * 64 + nt * 8 + tig * 2;
            atomicAdd(&C[(size_t)r0 * ldc + c],       acc[mt][nt][0]);
            atomicAdd(&C[(size_t)r0 * ldc + c + 1],   acc[mt][nt][1]);
            atomicAdd(&C[(size_t)(r0 + 8) * ldc + c],     acc[mt][nt][2]);
            atomicAdd(&C[(size_t)(r0 + 8) * ldc + c + 1], acc[mt][nt][3]);
        }
    }
}

// ---------------- small kernels ----------------
__global__ void zero_k(float* p, size_t n) {
    size_t i = (size_t)blockIdx.x * 256 + threadIdx.x;
    if (i < n) p[i] = 0.f;
}

__global__ void transpose_k(const float* __restrict__ in, float* __restrict__ out, int R, int C) {
    __shared__ float t[32][33];
    int c0 = blockIdx.x * 32, r0 = blockIdx.y * 32;
    int x = threadIdx.x, y = threadIdx.y;
    #pragma unroll
    for (int dy = 0; dy < 32; dy += 8)
        t[y + dy][x] = in[(size_t)(r0 + y + dy) * C + c0 + x];
    __syncthreads();
    #pragma unroll
    for (int dy = 0; dy < 32; dy += 8)
        out[(size_t)(c0 + y + dy) * R + r0 + x] = t[x][y + dy];
}

__global__ void shift_k(const float* __restrict__ seq, const float* __restrict__ proj,
                        float* __restrict__ buf_out) {
    size_t idx = (size_t)blockIdx.x * 256 + threadIdx.x;
    int u = (int)(idx & (CU - 1));
    int t = (int)((idx >> 8) & (CL - 1));
    int b = (int)(idx >> 15);
    float val = (t < CL - 1) ? seq[(size_t)b * CL * CU + (size_t)(t + 1) * CU + u]
                             : proj[(size_t)b * CU + u];
    buf_out[idx] = val;
}

// zb = b2 @ Wg + gb
__global__ void zb_k(const float* __restrict__ b2, const float* __restrict__ Wg,
                     const float* __restrict__ gb, float* __restrict__ zb) {
    int n = threadIdx.x;
    float s = gb[n];
    for (int k = 0; k < CU; k++) s += b2[k] * Wg[(size_t)k * CU + n];
    zb[n] = s;
}

__global__ void ln_fused_k(const float* __restrict__ z, const float* __restrict__ buf,
                           const float* __restrict__ g, const float* __restrict__ bb,
                           float* __restrict__ rec, float* __restrict__ dz) {
    __shared__ float sh[8];
    const int row = blockIdx.x, tid = threadIdx.x;
    const size_t base = (size_t)row * CU;
    const int yrow = row + (int)((unsigned)row / 127u) + 1;
    float v = z[base + tid];
    float m = block_reduce_256(v, sh) * (1.0f / CU);
    float d = v - m;
    float var = block_reduce_256(d * d, sh) * (1.0f / CU);
    float r = rsqrtf(var + 1e-3f);
    float xh = d * r;
    float gg = g[tid];
    float recv = gg * xh + bb[tid];
    rec[base + tid] = recv;
    float drec = (recv - buf[(size_t)yrow * CU + tid]) * DREC_SCALE;
    float dxh = drec * gg;
    float s1 = block_reduce_256(dxh, sh) * (1.0f / CU);
    float s2 = block_reduce_256(dxh * xh, sh) * (1.0f / CU);
    dz[base + tid] = r * (dxh - s1 - xh * s2);
}

__global__ void contrib_k(const float* __restrict__ rec, float* __restrict__ out) {
    const int b = blockIdx.x, u = threadIdx.x;
    const float* p = rec + (size_t)b * (CL - 1) * CU + u;
    float s = 0.f;
    for (int t = 0; t < CL - 1; t++) s += p[(size_t)t * CU];
    out[(size_t)b * CU + u] = s * (1.0f / (CL - 1));
}

// ---------------- launch ----------------
extern "C" void kernel_launch(void* const* d_in, const int* in_sizes, int n_in,
                              void* d_out, int out_size) {
    const float* inputs = (const float*)d_in[0];
    const float* seq  = (const float*)d_in[2];
    const float* Wp   = (const float*)d_in[3];
    const float* bp   = (const float*)d_in[4];
    const float* Wphi = (const float*)d_in[5];
    const float* bphi = (const float*)d_in[6];
    const float* Wpsi = (const float*)d_in[7];
    const float* bpsi = (const float*)d_in[8];
    const float* W1   = (const float*)d_in[9];
    const float* b1   = (const float*)d_in[10];
    const float* W2   = (const float*)d_in[11];
    const float* b2   = (const float*)d_in[12];
    const float* Wg   = (const float*)d_in[13];
    const float* gb   = (const float*)d_in[14];
    const float* lng  = (const float*)d_in[15];
    const float* lnb  = (const float*)d_in[16];
    const float* Wh   = (const float*)d_in[17];
    const float* hb   = (const float*)d_in[18];

    float* out = (float*)d_out;
    float* buf_out = out + (size_t)CB * CU;

    cudaFuncSetAttribute(gemm_nn_tc, cudaFuncAttributeMaxDynamicSharedMemorySize, GEMM_SMEM_BYTES);

    float* S = nullptr;
    cudaGetSymbolAddress((void**)&S, g_scratch);
    float *PHI = S + O_PHI, *Z = S + O_Z, *REC = S + O_REC, *DZ = S + O_DZ, *DE = S + O_DE;
    float *PRE = S + O_PRE, *H = S + O_H;
    float *DW1T = S + O_DW1T, *DW2T = S + O_DW2T, *DB1 = S + O_DB1, *DB2 = S + O_DB2;
    float *WpT = S + O_WPT, *WphiT = S + O_WPHIT, *W1T = S + O_W1T, *W2T = S + O_W2T;
    float *WgT = S + O_WGT, *WpsiT = S + O_WPSIT, *WhT = S + O_WHT;
    float *COMBT = S + O_COMBT, *ZB = S + O_ZB;
    float *PROJ = S + O_PROJ, *PSI = S + O_PSI, *PREPSI = S + O_PREPSI;
    float *HPSI = S + O_HPSI, *EPSI = S + O_EPSI, *CONTRIB = S + O_CONTRIB;

    { // zero dW1T,dW2T,db1,db2 (contiguous)
        size_t nz = (size_t)CH * CU + (size_t)CU * CH + CH + CU;
        zero_k<<<(unsigned)((nz + 255) / 256), 256>>>(DW1T, nz);
    }
    transpose_k<<<dim3(CU / 32, 128 / 32), dim3(32, 8)>>>(Wp,   WpT,   128, CU);
    transpose_k<<<dim3(CU / 32, CU / 32),  dim3(32, 8)>>>(Wphi, WphiT, CU, CU);
    transpose_k<<<dim3(CH / 32, CU / 32),  dim3(32, 8)>>>(W1,   W1T,   CU, CH);
    transpose_k<<<dim3(CU / 32, CH / 32),  dim3(32, 8)>>>(W2,   W2T,   CH, CU);
    transpose_k<<<dim3(CU / 32, CU / 32),  dim3(32, 8)>>>(Wg,   WgT,   CU, CU);
    transpose_k<<<dim3(CU / 32, CU / 32),  dim3(32, 8)>>>(Wpsi, WpsiT, CU, CU);
    transpose_k<<<dim3(CU / 32, CU / 32),  dim3(32, 8)>>>(Wh,   WhT,   CU, CU);

    // COMBT = (W2@Wg)^T = WgT @ W2^T   [256,1024]
    gemm_nn_tc<<<dim3(CH / 256, CU / 128), 256, GEMM_SMEM_BYTES>>>(WgT, nullptr, W2, nullptr, 0.f,
        nullptr, nullptr, 0.f, COMBT, nullptr, nullptr, nullptr, CU, CU, CU, CH, 0, 0);
    zb_k<<<1, 256>>>(b2, Wg, gb, ZB);

    // proj = inputs @ Wp + bp
    gemm_nn_tc<<<dim3(1, CB / 128), 256, GEMM_SMEM_BYTES>>>(inputs, nullptr, WpT, nullptr, 0.f,
        bp, nullptr, 0.f, PROJ, nullptr, nullptr, nullptr, 128, 128, 128, CU, 0, 0);

    shift_k<<<(CB * CL * CU) / 256, 256>>>(seq, PROJ, buf_out);

    // phi = X @ Wphi + bphi   (X gathered from buf)
    gemm_nn_tc<<<dim3(1, CNR / 128), 256, GEMM_SMEM_BYTES>>>(buf_out, nullptr, WphiT, nullptr, 0.f,
        bphi, nullptr, 0.f, PHI, nullptr, nullptr, nullptr, CU, CU, CU, CU, 0, 1);

    // pre = phi@W1+b1 ; H = gelu(pre)
    gemm_nn_tc<<<dim3(CH / 256, CNR / 128), 256, GEMM_SMEM_BYTES>>>(PHI, nullptr, W1T, nullptr, 0.f,
        b1, nullptr, 0.f, H, PRE, nullptr, nullptr, CU, CU, CU, CH, 1, 0);

    // z = H @ (W2@Wg) + (b2@Wg + gb)
    gemm_nn_tc<<<dim3(1, CNR / 128), 256, GEMM_SMEM_BYTES>>>(H, nullptr, COMBT, nullptr, 0.f,
        ZB, nullptr, 0.f, Z, nullptr, nullptr, nullptr, CH, CH, CH, CU, 0, 0);

    // rec = LN(z); dz = LN_bwd(...)  (y gathered from buf)
    ln_fused_k<<<CNR, 256>>>(Z, buf_out, lng, lnb, REC, DZ);

    // de = dz @ Wg^T  (+ db2 colsum fused)
    gemm_nn_tc<<<dim3(1, CNR / 128), 256, GEMM_SMEM_BYTES>>>(DZ, nullptr, Wg, nullptr, 0.f,
        nullptr, nullptr, 0.f, DE, nullptr, nullptr, DB2, CU, CU, CU, CU, 0, 0);

    // dW2T = de^T @ H
    gemm_tn_tc<<<dim3(CH / 256, CU / 128, 32), 256>>>(DE, H, DW2T, CNR, CU, CH, CH, 2032);

    // dpre = (de @ W2^T) * gelu'(pre)  (+ db1 colsum fused), in-place over PRE
    gemm_nn_tc<<<dim3(CH / 256, CNR / 128), 256, GEMM_SMEM_BYTES>>>(DE, nullptr, W2, nullptr, 0.f,
        nullptr, nullptr, 0.f, PRE, nullptr, PRE, DB1, CU, CU, CU, CH, 2, 0);

    // dW1T = dpre^T @ phi
    gemm_tn_tc<<<dim3(1, CH / 128, 32), 256>>>(PRE, PHI, DW1T, CNR, CH, CU, CU, 2032);

    contrib_k<<<CB, 256>>>(REC, CONTRIB);

    // psi = proj @ Wpsi + bpsi
    gemm_nn_tc<<<dim3(1, CB / 128), 256, GEMM_SMEM_BYTES>>>(PROJ, nullptr, WpsiT, nullptr, 0.f,
        bpsi, nullptr, 0.f, PSI, nullptr, nullptr, nullptr, CU, CU, CU, CU, 0, 0);

    // hpsi = gelu(psi @ (W1 - lr dW1) + (b1 - lr db1))
    gemm_nn_tc<<<dim3(CH / 256, CB / 128), 256, GEMM_SMEM_BYTES>>>(PSI, nullptr, W1T, DW1T, -LR,
        b1, DB1, -LR, HPSI, PREPSI, nullptr, nullptr, CU, CU, CU, CH, 1, 0);

    // epsi = hpsi @ (W2 - lr dW2) + (b2 - lr db2)
    gemm_nn_tc<<<dim3(1, CB / 128), 256, GEMM_SMEM_BYTES>>>(HPSI, nullptr, W2T, DW2T, -LR,
        b2, DB2, -LR, EPSI, nullptr, nullptr, nullptr, CH, CH, CH, CU, 0, 0);

    // out = (epsi + contrib) @ Wh + h_bias
    gemm_nn_tc<<<dim3(1, CB / 128), 256, GEMM_SMEM_BYTES>>>(EPSI, CONTRIB, WhT, nullptr, 0.f,
        hb, nullptr, 0.f, out, nullptr, nullptr, nullptr, CU, CU, CU, CU, 0, 0);

    (void)in_sizes; (void)n_in; (void)out_size;
}